// round 14
// baseline (speedup 1.0000x reference)
#include <cuda_runtime.h>
#include <cuda_bf16.h>
#include <math.h>
#include <stdint.h>

#define DD    256
#define RB    64          // z rows per CTA
#define CH    64          // memory cols per chunk
#define TPB   256
#define LAMBF 0.002f
#define EPSN  1e-10f
#define EPSS  1e-12f
#define MAXM  2048
#define NCHMX 32

// pre-swizzled bf16 operand tiles (scratch via __device__ globals)
__device__ __align__(16) __nv_bfloat16 g_mn[MAXM * DD];   // m_norm rows, ldmatrix swizzle
__device__ __align__(16) __nv_bfloat16 g_mt[MAXM * DD];   // mem^T chunk-blocked, ldmatrix swizzle

// ---------------- helpers ----------------
__device__ __forceinline__ uint32_t smem_u32(const void* p) {
    uint32_t a;
    asm("{ .reg .u64 t; cvta.to.shared.u64 t, %1; cvt.u32.u64 %0, t; }" : "=r"(a) : "l"(p));
    return a;
}

#define LDSM4(r0, r1, r2, r3, a) \
    asm volatile("ldmatrix.sync.aligned.m8n8.x4.shared.b16 {%0,%1,%2,%3}, [%4];" \
                 : "=r"(r0), "=r"(r1), "=r"(r2), "=r"(r3) : "r"(a))

#define MMA16816(d, A, b0, b1) \
    asm volatile("mma.sync.aligned.m16n8k16.row.col.f32.bf16.bf16.f32 " \
                 "{%0,%1,%2,%3},{%4,%5,%6,%7},{%8,%9},{%0,%1,%2,%3};" \
                 : "+f"((d)[0]), "+f"((d)[1]), "+f"((d)[2]), "+f"((d)[3]) \
                 : "r"((A)[0]), "r"((A)[1]), "r"((A)[2]), "r"((A)[3]), "r"(b0), "r"(b1))

#define CPASYNC16(dst, src) \
    asm volatile("cp.async.cg.shared.global [%0], [%1], 16;" :: "r"(dst), "l"(src) : "memory")
#define CPCOMMIT() asm volatile("cp.async.commit_group;" ::: "memory")
#define CPWAIT(n)  asm volatile("cp.async.wait_group %0;" :: "n"(n) : "memory")

#define STG16CS0(p) \
    asm volatile("st.global.cs.v4.b32 [%0], {%1,%1,%1,%1};" :: "l"(p), "r"(0u) : "memory")

__device__ __forceinline__ uint32_t bf2(float lo, float hi) {
    uint32_t r;
    asm("cvt.rn.bf16x2.f32 %0, %1, %2;" : "=r"(r) : "f"(hi), "f"(lo));
    return r;
}

__device__ __forceinline__ uint32_t encf(float x) {
    uint32_t u = __float_as_uint(x);
    return (u & 0x80000000u) ? ~u : (u | 0x80000000u);
}

// fast exp via MUFU: exp(x) = 2^(x*log2e). rel err ~1e-7; ex2(0) == 1.0f exactly.
__device__ __forceinline__ float fexp(float x) {
    float r;
    asm("ex2.approx.f32 %0, %1;" : "=f"(r) : "f"(x * 1.4426950408889634f));
    return r;
}

__device__ __forceinline__ float shrinkf(float w) {
    float d = w - LAMBF;
    return fmaxf(d, 0.f) * w / (fabsf(d) + EPSS);
}

// ---------------- prologue ----------------
__global__ void mm_prep(const float* __restrict__ mem, int M) {
    int m = blockIdx.x;
    int d = threadIdx.x;
    float v = (m < M) ? mem[(size_t)m * DD + d] : 0.f;
    float ss = v * v;
    #pragma unroll
    for (int o = 16; o; o >>= 1) ss += __shfl_xor_sync(0xffffffffu, ss, o);
    __shared__ float ws[8];
    __shared__ float sc;
    if ((d & 31) == 0) ws[d >> 5] = ss;
    __syncthreads();
    if (d == 0) {
        float t = 0.f;
        #pragma unroll
        for (int i = 0; i < 8; i++) t += ws[i];
        sc = sqrtf(t) + EPSN;
    }
    __syncthreads();
    g_mn[m * 256 + (((d >> 3) ^ (m & 7)) * 8) + (d & 7)] = __float2bfloat16(v / sc);
    int ch = m >> 6, c = m & 63;
    g_mt[ch * 16384 + d * 64 + (((c >> 3) ^ (d & 7)) * 8) + (c & 7)] = __float2bfloat16(v);
}

// ---------------- GEMM micro-kernels ----------------
__device__ __forceinline__ void gemm1_reg(const uint32_t* Areg, uint32_t sB, int wc, int lane,
                                          float acc[16]) {
    const uint32_t h = lane >> 4;
    const uint32_t brow = wc * 32 + (lane & 15);
    const uint32_t bbase = sB + brow * 512;
    const uint32_t brx = brow & 7;
    uint32_t p[4], q[4];
    LDSM4(p[0], p[1], p[2], p[3], bbase + ((h ^ brx) << 4));
    #pragma unroll
    for (int kk = 0; kk < 16; kk++) {
        uint32_t cb = ((uint32_t)(kk * 2 + h) ^ brx) << 4;
        LDSM4(q[0], q[1], q[2], q[3], bbase + 16 * 512 + cb);
        MMA16816(acc + 0, (Areg + 4 * kk), p[0], p[2]);
        MMA16816(acc + 4, (Areg + 4 * kk), p[1], p[3]);
        if (kk < 15) {
            uint32_t cbn = ((uint32_t)((kk + 1) * 2 + h) ^ brx) << 4;
            LDSM4(p[0], p[1], p[2], p[3], bbase + cbn);
        }
        MMA16816(acc + 8,  (Areg + 4 * kk), q[0], q[2]);
        MMA16816(acc + 12, (Areg + 4 * kk), q[1], q[3]);
    }
}

__device__ __forceinline__ void gemm1(uint32_t sA, uint32_t sB, int wr, int wc, int lane,
                                      float acc[16]) {
    const uint32_t h = lane >> 4;
    const uint32_t arow = wr * 16 + (lane & 15);
    const uint32_t abase = sA + arow * 512;
    const uint32_t arx = arow & 7;
    const uint32_t brow = wc * 32 + (lane & 15);
    const uint32_t bbase = sB + brow * 512;
    const uint32_t brx = brow & 7;
    #pragma unroll
    for (int kk = 0; kk < 16; kk++) {
        uint32_t ca = ((uint32_t)(kk * 2 + h) ^ arx) << 4;
        uint32_t cb = ((uint32_t)(kk * 2 + h) ^ brx) << 4;
        uint32_t A[4], p0, p1, p2, p3, q0, q1, q2, q3;
        LDSM4(A[0], A[1], A[2], A[3], abase + ca);
        LDSM4(p0, p1, p2, p3, bbase + cb);
        LDSM4(q0, q1, q2, q3, bbase + 16 * 512 + cb);
        MMA16816(acc + 0,  A, p0, p2);
        MMA16816(acc + 4,  A, p1, p3);
        MMA16816(acc + 8,  A, q0, q2);
        MMA16816(acc + 12, A, q1, q3);
    }
}

__device__ __forceinline__ void gemm2(uint32_t sP, uint32_t sB2, int wr, int wc, int lane,
                                      float zac[64]) {
    const uint32_t h = lane >> 4;
    const uint32_t prow = wr * 16 + (lane & 15);
    const uint32_t pbase = sP + prow * 128;
    const uint32_t prx = prow & 7;
    const uint32_t drow = wc * 128 + (lane & 15);
    const uint32_t dbase = sB2 + drow * 128;
    const uint32_t drx = drow & 7;
    #pragma unroll
    for (int kk = 0; kk < 4; kk++) {
        uint32_t ca = ((uint32_t)(kk * 2 + h) ^ prx) << 4;
        uint32_t cb = ((uint32_t)(kk * 2 + h) ^ drx) << 4;
        uint32_t A[4];
        LDSM4(A[0], A[1], A[2], A[3], pbase + ca);
        #pragma unroll
        for (int g = 0; g < 8; g++) {
            uint32_t b0, b1, b2, b3;
            LDSM4(b0, b1, b2, b3, dbase + g * 2048 + cb);
            MMA16816(zac + (g * 2) * 4,     A, b0, b2);
            MMA16816(zac + (g * 2 + 1) * 4, A, b1, b3);
        }
    }
}

__device__ __forceinline__ void copyB(uint32_t sdst, const __nv_bfloat16* g) {
    const char* gp = (const char*)g;
    #pragma unroll
    for (int k = 0; k < 8; k++) {
        int idx = threadIdx.x + k * 256;
        CPASYNC16(sdst + idx * 16, gp + (size_t)idx * 16);
    }
}

// smem offsets (bytes)
// Pass 1: THREE 32K B slabs (S0 = A region, reused after Areg hoist).
// Phase A (cold): S0 = rebuilt A tile, S1 = B1, S2 = memT, P aliases RMAX.
#define S0_OFF   0
#define S1_OFF   32768
#define S2_OFF   65536
#define RMAX_OFF 98304      // 32 chunks x 32 row-pairs x 4B = 4K; phase A: P tile
#define P_OFF    98304
#define TENC_OFF 106496     // 32 pair-min thresholds x 4B
#define FLG_OFF  106752     // 32 x 4B
#define RED_OFF  106880     // 512 floats
#define ZS_OFF   108928
#define TS_OFF   109184
#define SS_OFF   109440
#define SM_TOT   109696

__global__ __launch_bounds__(TPB, 2) void mm_main(
    const float* __restrict__ z,
    float* __restrict__ wout,     // [N, M]
    float* __restrict__ zhat,     // [N, 256]
    int M, int NCH)
{
    extern __shared__ char smc[];
    const uint32_t sbase = smem_u32(smc);
    uint32_t* rmaxP = (uint32_t*)(smc + RMAX_OFF);
    uint32_t* tencP = (uint32_t*)(smc + TENC_OFF);
    int*      flg  = (int*)(smc + FLG_OFF);
    float*    red  = (float*)(smc + RED_OFF);
    float*    Zs   = (float*)(smc + ZS_OFF);
    float*    Ts   = (float*)(smc + TS_OFF);
    float*    Ss   = (float*)(smc + SS_OFF);

    const int tid = threadIdx.x, wid = tid >> 5, lane = tid & 31;
    const int wr = wid >> 1, wc = wid & 1;
    const long long gr0 = (long long)blockIdx.x * RB;
    const int r0l = wr * 16 + (lane >> 2), r1l = r0l + 8;
    const int pr  = wr * 8 + (lane >> 2);   // row-pair index

    const uint32_t sS0 = sbase + S0_OFF, sS1 = sbase + S1_OFF, sS2 = sbase + S2_OFF;

    // ---- init rmaxP, build A tile (in S0) ----
    for (int i = tid; i < NCH * 32; i += TPB) rmaxP[i] = 0u;
    #pragma unroll 1
    for (int i = 0; i < 8; i++) {
        int r = wid * 8 + i;
        const float4* zr = (const float4*)(z + (gr0 + r) * DD);
        float4 a = zr[lane * 2], b = zr[lane * 2 + 1];
        float ss = a.x*a.x + a.y*a.y + a.z*a.z + a.w*a.w
                 + b.x*b.x + b.y*b.y + b.z*b.z + b.w*b.w;
        #pragma unroll
        for (int o = 16; o; o >>= 1) ss += __shfl_xor_sync(0xffffffffu, ss, o);
        float inv = 1.f / (sqrtf(ss) + EPSN);
        uint4 u;
        u.x = bf2(a.x * inv, a.y * inv); u.y = bf2(a.z * inv, a.w * inv);
        u.z = bf2(b.x * inv, b.y * inv); u.w = bf2(b.z * inv, b.w * inv);
        *(uint4*)(smc + S0_OFF + r * 512 + ((lane ^ (r & 7)) * 16)) = u;
    }
    __syncthreads();

    // ---- hoist A fragments to registers; A's SMEM becomes slab S0 afterwards ----
    uint32_t Areg[64];
    {
        const uint32_t h = lane >> 4;
        const uint32_t arow = wr * 16 + (lane & 15);
        const uint32_t abase = sS0 + arow * 512;
        const uint32_t arx = arow & 7;
        #pragma unroll
        for (int kk = 0; kk < 16; kk++) {
            uint32_t ca = ((uint32_t)(kk * 2 + h) ^ arx) << 4;
            LDSM4(Areg[4*kk], Areg[4*kk+1], Areg[4*kk+2], Areg[4*kk+3], abase + ca);
        }
    }
    __syncthreads();   // all warps done reading A before S0 is overwritten

    // ---- hoisted zero-fill row pointers ----
    float4* fp[4];
    {
        int cb = (tid & 15) * 4;
        #pragma unroll
        for (int k = 0; k < 4; k++)
            fp[k] = (float4*)(wout + (gr0 + (tid >> 4) + k * 16) * (long long)M + cb);
    }
    const int cbase = (tid & 15) * 4;

    // ================= PASS 1: 3-slab rotation, prefetch depth 2 =================
    float z0 = 0.f, z1 = 0.f;
    copyB(sS0, g_mn); CPCOMMIT();
    if (NCH > 1) { copyB(sS1, g_mn + (size_t)CH * DD); CPCOMMIT(); }
    for (int ch = 0; ch < NCH; ch++) {
        if (ch + 1 < NCH) { CPWAIT(1); } else { CPWAIT(0); }   // copy(ch) complete
        __syncthreads();   // publishes copy(ch); proves gemm(ch-1) freed slab (ch+2)%3
        if (ch + 2 < NCH) {
            uint32_t d = (ch + 2) % 3;
            copyB(d == 0 ? sS0 : (d == 1 ? sS1 : sS2), g_mn + (size_t)(ch + 2) * CH * DD);
            CPCOMMIT();
        }
        // zero-fill this chunk's w_hat region (evict-first; overlaps gemm warm-up)
        if (ch * CH + cbase < M) {   // M % 4 == 0
            #pragma unroll
            for (int k = 0; k < 4; k++) STG16CS0(fp[k]);
        }
        #pragma unroll
        for (int k = 0; k < 4; k++) fp[k] += CH / 4;
        float acc[16] = {};
        uint32_t s = (ch % 3);
        gemm1_reg(Areg, s == 0 ? sS0 : (s == 1 ? sS1 : sS2), wc, lane, acc);
        float m = acc[0];
        #pragma unroll
        for (int nt = 0; nt < 4; nt++) {
            z0 += fexp(acc[nt * 4 + 0]) + fexp(acc[nt * 4 + 1]);
            z1 += fexp(acc[nt * 4 + 2]) + fexp(acc[nt * 4 + 3]);
            m = fmaxf(m, fmaxf(fmaxf(acc[nt * 4 + 0], acc[nt * 4 + 1]),
                               fmaxf(acc[nt * 4 + 2], acc[nt * 4 + 3])));
        }
        m = fmaxf(m, __shfl_xor_sync(0xffffffffu, m, 1));
        m = fmaxf(m, __shfl_xor_sync(0xffffffffu, m, 2));
        if ((lane & 3) == 0)
            atomicMax(&rmaxP[ch * 32 + pr], encf(m));
    }
    __syncthreads();
    red[r0l * 8 + wc * 4 + (lane & 3)] = z0;
    red[r1l * 8 + wc * 4 + (lane & 3)] = z1;
    __syncthreads();
    const float padc = (float)(NCH * CH - M);
    if (tid < 64) {
        float s = 0.f;
        #pragma unroll
        for (int j = 0; j < 8; j++) s += red[tid * 8 + j];
        s -= padc;                           // remove exact pad contribution (fexp(0)==1)
        Zs[tid] = 1.0f / s;
        Ts[tid] = logf(LAMBF * s) - 1e-3f;   // conservative skip threshold
    }
    __syncthreads();
    if (tid < 32) {   // pair-min thresholds (strictly more conservative)
        int row0 = (tid >> 3) * 16 + (tid & 7);
        tencP[tid] = encf(fminf(Ts[row0], Ts[row0 + 8]));
    }
    __syncthreads();
    if (tid < NCH) {
        int f = 0;
        #pragma unroll 4
        for (int p = 0; p < 32; p++) f |= (rmaxP[tid * 32 + p] > tencP[p]);
        flg[tid] = f;
    }
    const int anyflag = __syncthreads_or((tid < NCH) ? flg[tid] : 0);

    // ================= PHASE A (rare): flagged chunks =================
    const float invZ0 = Zs[r0l], invZ1 = Zs[r1l];
    const float T0 = Ts[r0l],    T1 = Ts[r1l];
    float s0 = 0.f, s1 = 0.f;
    float zac[64] = {};
    if (anyflag) {
        // rebuild A tile in S0 (it was recycled as a B slab during pass 1)
        #pragma unroll 1
        for (int i = 0; i < 8; i++) {
            int r = wid * 8 + i;
            const float4* zr = (const float4*)(z + (gr0 + r) * DD);
            float4 a = zr[lane * 2], b = zr[lane * 2 + 1];
            float ss = a.x*a.x + a.y*a.y + a.z*a.z + a.w*a.w
                     + b.x*b.x + b.y*b.y + b.z*b.z + b.w*b.w;
            #pragma unroll
            for (int o = 16; o; o >>= 1) ss += __shfl_xor_sync(0xffffffffu, ss, o);
            float inv = 1.f / (sqrtf(ss) + EPSN);
            uint4 u;
            u.x = bf2(a.x * inv, a.y * inv); u.y = bf2(a.z * inv, a.w * inv);
            u.z = bf2(b.x * inv, b.y * inv); u.w = bf2(b.z * inv, b.w * inv);
            *(uint4*)(smc + S0_OFF + r * 512 + ((lane ^ (r & 7)) * 16)) = u;
        }
        __syncthreads();
        for (int ch = 0; ch < NCH; ch++) {
            if (!flg[ch]) continue;
            copyB(sS1, g_mn + (size_t)ch * CH * DD);
            CPCOMMIT(); CPWAIT(0);
            __syncthreads();
            float acc[16] = {};
            gemm1(sS0, sS1, wr, wc, lane, acc);
            float* w0 = wout + (gr0 + r0l) * (long long)M;
            float* w1 = wout + (gr0 + r1l) * (long long)M;
            #pragma unroll
            for (int nt = 0; nt < 4; nt++) {
                int cl  = wc * 32 + nt * 8 + 2 * (lane & 3);
                int col = ch * CH + cl;
                float h00 = 0.f, h01 = 0.f, h10 = 0.f, h11 = 0.f;
                if (col < M) {
                    float a0 = acc[nt*4+0], a1 = acc[nt*4+1], a2 = acc[nt*4+2], a3 = acc[nt*4+3];
                    if (a0 > T0) h00 = shrinkf(fexp(a0) * invZ0);
                    if (a1 > T0) h01 = shrinkf(fexp(a1) * invZ0);
                    if (a2 > T1) h10 = shrinkf(fexp(a2) * invZ1);
                    if (a3 > T1) h11 = shrinkf(fexp(a3) * invZ1);
                    s0 += h00 + h01; s1 += h10 + h11;
                    *(float2*)(w0 + col) = make_float2(h00, h01);   // unnormalized
                    *(float2*)(w1 + col) = make_float2(h10, h11);
                }
                *(uint32_t*)(smc + P_OFF + r0l * 128 + (((cl >> 3) ^ (r0l & 7)) << 4) + (cl & 7) * 2)
                    = bf2(h00, h01);
                *(uint32_t*)(smc + P_OFF + r1l * 128 + (((cl >> 3) ^ (r1l & 7)) << 4) + (cl & 7) * 2)
                    = bf2(h10, h11);
            }
            __syncthreads();
            copyB(sS2, g_mt + (size_t)ch * CH * DD);
            CPCOMMIT(); CPWAIT(0);
            __syncthreads();
            gemm2(sbase + P_OFF, sS2, wr, wc, lane, zac);
            __syncthreads();
        }
    }

    // ---- S reduction ----
    red[r0l * 8 + wc * 4 + (lane & 3)] = s0;
    red[r1l * 8 + wc * 4 + (lane & 3)] = s1;
    __syncthreads();
    if (tid < 64) {
        float s = 0.f;
        #pragma unroll
        for (int j = 0; j < 8; j++) s += red[tid * 8 + j];
        Ss[tid] = 1.0f / (s + EPSS);
    }
    __syncthreads();

    // ---- fixup flagged chunks: w_hat *= invS ----
    if (anyflag) {
        for (int ch = 0; ch < NCH; ch++) {
            if (!flg[ch]) continue;
            for (int idx = tid; idx < 64 * 16; idx += TPB) {
                int r = idx >> 4;
                int c4 = ch * CH + (idx & 15) * 4;
                if (c4 < M) {
                    float4* p = (float4*)(wout + (gr0 + r) * (long long)M + c4);
                    float4 v = *p; float s = Ss[r];
                    v.x *= s; v.y *= s; v.z *= s; v.w *= s;
                    *p = v;
                }
            }
        }
        __syncthreads();
    }

    // ---- z_hat epilogue ----
    {
        const float invS0 = Ss[r0l], invS1 = Ss[r1l];
        float* zr0 = zhat + (gr0 + r0l) * DD;
        float* zr1 = zhat + (gr0 + r1l) * DD;
        #pragma unroll
        for (int g = 0; g < 8; g++) {
            #pragma unroll
            for (int t = 0; t < 2; t++) {
                int d = wc * 128 + g * 16 + t * 8 + 2 * (lane & 3);
                int ii = (g * 2 + t) * 4;
                *(float2*)(zr0 + d) = make_float2(zac[ii + 0] * invS0, zac[ii + 1] * invS0);
                *(float2*)(zr1 + d) = make_float2(zac[ii + 2] * invS1, zac[ii + 3] * invS1);
            }
        }
    }
}

// ---------------- host ----------------
extern "C" void kernel_launch(void* const* d_in, const int* in_sizes, int n_in,
                              void* d_out, int out_size) {
    const float* z   = (const float*)d_in[0];
    const float* mem = (const float*)d_in[1];
    const int N = in_sizes[0] / DD;
    const int M = in_sizes[1] / DD;
    const int NCH = (M + CH - 1) / CH;

    float* zhat = (float*)d_out;                 // [N, 256]
    float* wout = zhat + (size_t)N * DD;         // [N, M]

    cudaFuncSetAttribute(mm_main, cudaFuncAttributeMaxDynamicSharedMemorySize, SM_TOT);

    mm_prep<<<NCH * CH, 256>>>(mem, M);
    mm_main<<<N / RB, TPB, SM_TOT>>>(z, wout, zhat, M, NCH);
}

// round 15
// speedup vs baseline: 1.0508x; 1.0508x over previous
#include <cuda_runtime.h>
#include <cuda_bf16.h>
#include <math.h>
#include <stdint.h>

#define DD    256
#define RB    64          // z rows per CTA
#define CH    64          // memory cols per chunk
#define TPB   256
#define LAMBF 0.002f
#define EPSN  1e-10f
#define EPSS  1e-12f
#define MAXM  2048
#define NCHMX 32

// pre-swizzled bf16 operand tiles (scratch via __device__ globals)
__device__ __align__(16) __nv_bfloat16 g_mn[MAXM * DD];   // m_norm rows, ldmatrix swizzle
__device__ __align__(16) __nv_bfloat16 g_mt[MAXM * DD];   // mem^T chunk-blocked, ldmatrix swizzle

// ---------------- helpers ----------------
__device__ __forceinline__ uint32_t smem_u32(const void* p) {
    uint32_t a;
    asm("{ .reg .u64 t; cvta.to.shared.u64 t, %1; cvt.u32.u64 %0, t; }" : "=r"(a) : "l"(p));
    return a;
}

#define LDSM4(r0, r1, r2, r3, a) \
    asm volatile("ldmatrix.sync.aligned.m8n8.x4.shared.b16 {%0,%1,%2,%3}, [%4];" \
                 : "=r"(r0), "=r"(r1), "=r"(r2), "=r"(r3) : "r"(a))

#define MMA16816(d, A, b0, b1) \
    asm volatile("mma.sync.aligned.m16n8k16.row.col.f32.bf16.bf16.f32 " \
                 "{%0,%1,%2,%3},{%4,%5,%6,%7},{%8,%9},{%0,%1,%2,%3};" \
                 : "+f"((d)[0]), "+f"((d)[1]), "+f"((d)[2]), "+f"((d)[3]) \
                 : "r"((A)[0]), "r"((A)[1]), "r"((A)[2]), "r"((A)[3]), "r"(b0), "r"(b1))

#define CPASYNC16(dst, src) \
    asm volatile("cp.async.cg.shared.global [%0], [%1], 16;" :: "r"(dst), "l"(src) : "memory")
#define CPCOMMIT() asm volatile("cp.async.commit_group;" ::: "memory")
#define CPWAIT(n)  asm volatile("cp.async.wait_group %0;" :: "n"(n) : "memory")

__device__ __forceinline__ uint32_t bf2(float lo, float hi) {
    uint32_t r;
    asm("cvt.rn.bf16x2.f32 %0, %1, %2;" : "=r"(r) : "f"(hi), "f"(lo));
    return r;
}

// order-preserving float<->uint encode (atomicMax/Min on signed floats)
__device__ __forceinline__ uint32_t encf(float x) {
    uint32_t u = __float_as_uint(x);
    return (u & 0x80000000u) ? ~u : (u | 0x80000000u);
}
__device__ __forceinline__ float decf(uint32_t e) {
    uint32_t u = (e & 0x80000000u) ? (e ^ 0x80000000u) : ~e;
    return __uint_as_float(u);
}

// fast exp via MUFU (fallback path only): rel err ~1e-7; ex2(0)==1.0f exactly
__device__ __forceinline__ float fexp(float x) {
    float r;
    asm("ex2.approx.f32 %0, %1;" : "=f"(r) : "f"(x * 1.4426950408889634f));
    return r;
}

__device__ __forceinline__ float shrinkf(float w) {
    float d = w - LAMBF;
    return fmaxf(d, 0.f) * w / (fabsf(d) + EPSS);
}

// ---------------- prologue ----------------
__global__ void mm_prep(const float* __restrict__ mem, int M) {
    int m = blockIdx.x;
    int d = threadIdx.x;
    float v = (m < M) ? mem[(size_t)m * DD + d] : 0.f;
    float ss = v * v;
    #pragma unroll
    for (int o = 16; o; o >>= 1) ss += __shfl_xor_sync(0xffffffffu, ss, o);
    __shared__ float ws[8];
    __shared__ float sc;
    if ((d & 31) == 0) ws[d >> 5] = ss;
    __syncthreads();
    if (d == 0) {
        float t = 0.f;
        #pragma unroll
        for (int i = 0; i < 8; i++) t += ws[i];
        sc = sqrtf(t) + EPSN;
    }
    __syncthreads();
    g_mn[m * 256 + (((d >> 3) ^ (m & 7)) * 8) + (d & 7)] = __float2bfloat16(v / sc);
    int ch = m >> 6, c = m & 63;
    g_mt[ch * 16384 + d * 64 + (((c >> 3) ^ (d & 7)) * 8) + (c & 7)] = __float2bfloat16(v);
}

// ---------------- GEMM micro-kernels (R10 proven) ----------------
__device__ __forceinline__ void gemm1_reg(const uint32_t* Areg, uint32_t sB, int wc, int lane,
                                          float acc[16]) {
    const uint32_t h = lane >> 4;
    const uint32_t brow = wc * 32 + (lane & 15);
    const uint32_t bbase = sB + brow * 512;
    const uint32_t brx = brow & 7;
    uint32_t p[4], q[4];
    LDSM4(p[0], p[1], p[2], p[3], bbase + ((h ^ brx) << 4));
    #pragma unroll
    for (int kk = 0; kk < 16; kk++) {
        uint32_t cb = ((uint32_t)(kk * 2 + h) ^ brx) << 4;
        LDSM4(q[0], q[1], q[2], q[3], bbase + 16 * 512 + cb);
        MMA16816(acc + 0, (Areg + 4 * kk), p[0], p[2]);
        MMA16816(acc + 4, (Areg + 4 * kk), p[1], p[3]);
        if (kk < 15) {
            uint32_t cbn = ((uint32_t)((kk + 1) * 2 + h) ^ brx) << 4;
            LDSM4(p[0], p[1], p[2], p[3], bbase + cbn);
        }
        MMA16816(acc + 8,  (Areg + 4 * kk), q[0], q[2]);
        MMA16816(acc + 12, (Areg + 4 * kk), q[1], q[3]);
    }
}

__device__ __forceinline__ void gemm2(uint32_t sP, uint32_t sB2, int wr, int wc, int lane,
                                      float zac[64]) {
    const uint32_t h = lane >> 4;
    const uint32_t prow = wr * 16 + (lane & 15);
    const uint32_t pbase = sP + prow * 128;
    const uint32_t prx = prow & 7;
    const uint32_t drow = wc * 128 + (lane & 15);
    const uint32_t dbase = sB2 + drow * 128;
    const uint32_t drx = drow & 7;
    #pragma unroll
    for (int kk = 0; kk < 4; kk++) {
        uint32_t ca = ((uint32_t)(kk * 2 + h) ^ prx) << 4;
        uint32_t cb = ((uint32_t)(kk * 2 + h) ^ drx) << 4;
        uint32_t A[4];
        LDSM4(A[0], A[1], A[2], A[3], pbase + ca);
        #pragma unroll
        for (int g = 0; g < 8; g++) {
            uint32_t b0, b1, b2, b3;
            LDSM4(b0, b1, b2, b3, dbase + g * 2048 + cb);
            MMA16816(zac + (g * 2) * 4,     A, b0, b2);
            MMA16816(zac + (g * 2 + 1) * 4, A, b1, b3);
        }
    }
}

__device__ __forceinline__ void copyB(uint32_t sdst, const __nv_bfloat16* g) {
    const char* gp = (const char*)g;
    #pragma unroll
    for (int k = 0; k < 8; k++) {
        int idx = threadIdx.x + k * 256;
        CPASYNC16(sdst + idx * 16, gp + (size_t)idx * 16);
    }
}

// smem offsets (bytes) — R10 layout + RMIN; P aliases RMAX/RMIN (used after flags fixed)
#define A_OFF    0          // A tile (32K), intact for whole kernel
#define B1A_OFF  32768      // B dbl
#define B1B_OFF  65536
#define RMAX_OFF 98304      // 32 chunks x 32 pairs x 4B = 4K
#define RMIN_OFF 102400     // 32 pairs x 4B
#define P_OFF    98304      // phase A P tile (8K), aliases RMAX+RMIN
#define TENC_OFF 106496     // 32 x 4B
#define FLG_OFF  106752     // 32 x 4B
#define RED_OFF  106880     // 512 floats
#define ZS_OFF   108928
#define TS_OFF   109184
#define SS_OFF   109440
#define SM_TOT   109696

__global__ __launch_bounds__(TPB, 2) void mm_main(
    const float* __restrict__ z,
    float* __restrict__ wout,     // [N, M]
    float* __restrict__ zhat,     // [N, 256]
    int M, int NCH)
{
    extern __shared__ char smc[];
    const uint32_t sbase = smem_u32(smc);
    uint32_t* rmaxP = (uint32_t*)(smc + RMAX_OFF);
    uint32_t* rminP = (uint32_t*)(smc + RMIN_OFF);
    uint32_t* tencP = (uint32_t*)(smc + TENC_OFF);
    int*      flg  = (int*)(smc + FLG_OFF);
    float*    red  = (float*)(smc + RED_OFF);
    float*    Zs   = (float*)(smc + ZS_OFF);
    float*    Ts   = (float*)(smc + TS_OFF);
    float*    Ss   = (float*)(smc + SS_OFF);

    const int tid = threadIdx.x, wid = tid >> 5, lane = tid & 31;
    const int wr = wid >> 1, wc = wid & 1;
    const long long gr0 = (long long)blockIdx.x * RB;
    const int r0l = wr * 16 + (lane >> 2), r1l = r0l + 8;
    const int pr  = wr * 8 + (lane >> 2);   // row-pair index

    const uint32_t sA = sbase + A_OFF;

    // ---- init rmaxP/rminP, build A tile ----
    for (int i = tid; i < NCH * 32; i += TPB) rmaxP[i] = 0u;
    if (tid < 32) rminP[tid] = 0xFFFFFFFFu;
    #pragma unroll 1
    for (int i = 0; i < 8; i++) {
        int r = wid * 8 + i;
        const float4* zr = (const float4*)(z + (gr0 + r) * DD);
        float4 a = zr[lane * 2], b = zr[lane * 2 + 1];
        float ss = a.x*a.x + a.y*a.y + a.z*a.z + a.w*a.w
                 + b.x*b.x + b.y*b.y + b.z*b.z + b.w*b.w;
        #pragma unroll
        for (int o = 16; o; o >>= 1) ss += __shfl_xor_sync(0xffffffffu, ss, o);
        float inv = 1.f / (sqrtf(ss) + EPSN);
        uint4 u;
        u.x = bf2(a.x * inv, a.y * inv); u.y = bf2(a.z * inv, a.w * inv);
        u.z = bf2(b.x * inv, b.y * inv); u.w = bf2(b.z * inv, b.w * inv);
        *(uint4*)(smc + A_OFF + r * 512 + ((lane ^ (r & 7)) * 16)) = u;
    }
    __syncthreads();

    // ---- hoist A fragments to registers (A tile stays intact in SMEM) ----
    uint32_t Areg[64];
    {
        const uint32_t h = lane >> 4;
        const uint32_t arow = wr * 16 + (lane & 15);
        const uint32_t abase = sA + arow * 512;
        const uint32_t arx = arow & 7;
        #pragma unroll
        for (int kk = 0; kk < 16; kk++) {
            uint32_t ca = ((uint32_t)(kk * 2 + h) ^ arx) << 4;
            LDSM4(Areg[4*kk], Areg[4*kk+1], Areg[4*kk+2], Areg[4*kk+3], abase + ca);
        }
    }

    // ---- hoisted zero-fill row pointers (advanced by CH per chunk) ----
    float4* fp[4];
    {
        int cb = (tid & 15) * 4;
        #pragma unroll
        for (int k = 0; k < 4; k++)
            fp[k] = (float4*)(wout + (gr0 + (tid >> 4) + k * 16) * (long long)M + cb);
    }
    const int cbase = (tid & 15) * 4;

    // ================= PASS 1: GEMM1; max/min tracking (NO fexp/Z); zero-fill ==========
    // Sound skip bound: w = exp(s)/Z <= exp(s - s_min)/M, so a chunk is all-zero if
    // s_max(chunk) - s_min(global) <= ln(lambda*M) - margin. Z itself is NOT needed
    // unless some chunk fails this test (rare path recomputes exact Z below).
    float mn = 3.f;   // running global min over this thread's sims (pads give 0: safe)
    copyB(sbase + B1A_OFF, g_mn); CPCOMMIT();
    for (int ch = 0; ch < NCH; ch++) {
        CPWAIT(0);
        __syncthreads();   // publishes copy(ch); proves gemm(ch-1) drained other buffer
        if (ch + 1 < NCH) {
            copyB(sbase + (((ch + 1) & 1) ? B1B_OFF : B1A_OFF),
                  g_mn + (size_t)(ch + 1) * CH * DD);
            CPCOMMIT();
        }
        // zero-fill this chunk's w_hat region (overlaps gemm LDSM warm-up)
        if (ch * CH + cbase < M) {   // M % 4 == 0
            const float4 zero4 = make_float4(0.f, 0.f, 0.f, 0.f);
            #pragma unroll
            for (int k = 0; k < 4; k++) *fp[k] = zero4;
        }
        #pragma unroll
        for (int k = 0; k < 4; k++) fp[k] += CH / 4;
        float acc[16] = {};
        gemm1_reg(Areg, sbase + ((ch & 1) ? B1B_OFF : B1A_OFF), wc, lane, acc);
        float m = acc[0];
        #pragma unroll
        for (int nt = 0; nt < 4; nt++) {
            float u0 = fmaxf(acc[nt * 4 + 0], acc[nt * 4 + 1]);
            float u1 = fmaxf(acc[nt * 4 + 2], acc[nt * 4 + 3]);
            float v0 = fminf(acc[nt * 4 + 0], acc[nt * 4 + 1]);
            float v1 = fminf(acc[nt * 4 + 2], acc[nt * 4 + 3]);
            m  = fmaxf(m,  fmaxf(u0, u1));
            mn = fminf(mn, fminf(v0, v1));
        }
        m = fmaxf(m, __shfl_xor_sync(0xffffffffu, m, 1));
        m = fmaxf(m, __shfl_xor_sync(0xffffffffu, m, 2));
        if ((lane & 3) == 0)
            atomicMax(&rmaxP[ch * 32 + pr], encf(m));
    }
    // reduce running min per pair
    mn = fminf(mn, __shfl_xor_sync(0xffffffffu, mn, 1));
    mn = fminf(mn, __shfl_xor_sync(0xffffffffu, mn, 2));
    if ((lane & 3) == 0)
        atomicMin(&rminP[pr], encf(mn));
    __syncthreads();
    // loose per-pair thresholds: T_p = ln(lambda*M) + s_min_pair - margin
    const float lnLM = logf(LAMBF * (float)M);
    if (tid < 32)
        tencP[tid] = encf(lnLM + decf(rminP[tid]) - 1e-3f);
    __syncthreads();
    if (tid < NCH) {
        int f = 0;
        #pragma unroll 4
        for (int p = 0; p < 32; p++) f |= (rmaxP[tid * 32 + p] > tencP[p]);
        flg[tid] = f;
    }
    const int anyflag = __syncthreads_or((tid < NCH) ? flg[tid] : 0);

    // ================= FALLBACK + PHASE A (rare): exact Z, exact flags, outputs ========
    float s0 = 0.f, s1 = 0.f;
    float zac[64] = {};
    if (anyflag) {
        // exact Z pass (fexp), reusing Areg + B double-buffer; sims bit-identical to pass 1
        float z0 = 0.f, z1 = 0.f;
        copyB(sbase + B1A_OFF, g_mn); CPCOMMIT();
        for (int ch = 0; ch < NCH; ch++) {
            CPWAIT(0);
            __syncthreads();
            if (ch + 1 < NCH) {
                copyB(sbase + (((ch + 1) & 1) ? B1B_OFF : B1A_OFF),
                      g_mn + (size_t)(ch + 1) * CH * DD);
                CPCOMMIT();
            }
            float acc[16] = {};
            gemm1_reg(Areg, sbase + ((ch & 1) ? B1B_OFF : B1A_OFF), wc, lane, acc);
            #pragma unroll
            for (int nt = 0; nt < 4; nt++) {
                z0 += fexp(acc[nt * 4 + 0]) + fexp(acc[nt * 4 + 1]);
                z1 += fexp(acc[nt * 4 + 2]) + fexp(acc[nt * 4 + 3]);
            }
        }
        __syncthreads();
        red[r0l * 8 + wc * 4 + (lane & 3)] = z0;
        red[r1l * 8 + wc * 4 + (lane & 3)] = z1;
        __syncthreads();
        const float padc = (float)(NCH * CH - M);
        if (tid < 64) {
            float s = 0.f;
            #pragma unroll
            for (int j = 0; j < 8; j++) s += red[tid * 8 + j];
            s -= padc;                           // pads exact: sim 0 -> fexp 1
            Zs[tid] = 1.0f / s;
            Ts[tid] = logf(LAMBF * s) - 1e-3f;   // exact conservative threshold
        }
        __syncthreads();
        if (tid < 32) {
            int row0 = (tid >> 3) * 16 + (tid & 7);
            tencP[tid] = encf(fminf(Ts[row0], Ts[row0 + 8]));
        }
        __syncthreads();
        if (tid < NCH) {
            int f = 0;
            #pragma unroll 4
            for (int p = 0; p < 32; p++) f |= (rmaxP[tid * 32 + p] > tencP[p]);
            flg[tid] = f;
        }
        __syncthreads();

        const float invZ0 = Zs[r0l], invZ1 = Zs[r1l];
        const float T0 = Ts[r0l],    T1 = Ts[r1l];
        for (int ch = 0; ch < NCH; ch++) {
            if (!flg[ch]) continue;
            copyB(sbase + B1A_OFF, g_mn + (size_t)ch * CH * DD);
            CPCOMMIT(); CPWAIT(0);
            __syncthreads();
            float acc[16] = {};
            gemm1_reg(Areg, sbase + B1A_OFF, wc, lane, acc);   // bit-identical sims
            float* w0 = wout + (gr0 + r0l) * (long long)M;
            float* w1 = wout + (gr0 + r1l) * (long long)M;
            #pragma unroll
            for (int nt = 0; nt < 4; nt++) {
                int cl  = wc * 32 + nt * 8 + 2 * (lane & 3);
                int col = ch * CH + cl;
                float h00 = 0.f, h01 = 0.f, h10 = 0.f, h11 = 0.f;
                if (col < M) {
                    float a0 = acc[nt*4+0], a1 = acc[nt*4+1], a2 = acc[nt*4+2], a3 = acc[nt*4+3];
                    if (a0 > T0) h00 = shrinkf(fexp(a0) * invZ0);
                    if (a1 > T0) h01 = shrinkf(fexp(a1) * invZ0);
                    if (a2 > T1) h10 = shrinkf(fexp(a2) * invZ1);
                    if (a3 > T1) h11 = shrinkf(fexp(a3) * invZ1);
                    s0 += h00 + h01; s1 += h10 + h11;
                    *(float2*)(w0 + col) = make_float2(h00, h01);   // unnormalized
                    *(float2*)(w1 + col) = make_float2(h10, h11);
                }
                *(uint32_t*)(smc + P_OFF + r0l * 128 + (((cl >> 3) ^ (r0l & 7)) << 4) + (cl & 7) * 2)
                    = bf2(h00, h01);
                *(uint32_t*)(smc + P_OFF + r1l * 128 + (((cl >> 3) ^ (r1l & 7)) << 4) + (cl & 7) * 2)
                    = bf2(h10, h11);
            }
            __syncthreads();
            copyB(sbase + B1B_OFF, g_mt + (size_t)ch * CH * DD);
            CPCOMMIT(); CPWAIT(0);
            __syncthreads();
            gemm2(sbase + P_OFF, sbase + B1B_OFF, wr, wc, lane, zac);
            __syncthreads();
        }
    }

    // ---- S reduction ----
    red[r0l * 8 + wc * 4 + (lane & 3)] = s0;
    red[r1l * 8 + wc * 4 + (lane & 3)] = s1;
    __syncthreads();
    if (tid < 64) {
        float s = 0.f;
        #pragma unroll
        for (int j = 0; j < 8; j++) s += red[tid * 8 + j];
        Ss[tid] = 1.0f / (s + EPSS);
    }
    __syncthreads();

    // ---- fixup flagged chunks: w_hat *= invS ----
    if (anyflag) {
        for (int ch = 0; ch < NCH; ch++) {
            if (!flg[ch]) continue;
            for (int idx = tid; idx < 64 * 16; idx += TPB) {
                int r = idx >> 4;
                int c4 = ch * CH + (idx & 15) * 4;
                if (c4 < M) {
                    float4* p = (float4*)(wout + (gr0 + r) * (long long)M + c4);
                    float4 v = *p; float s = Ss[r];
                    v.x *= s; v.y *= s; v.z *= s; v.w *= s;
                    *p = v;
                }
            }
        }
        __syncthreads();
    }

    // ---- z_hat epilogue (zac==0 on fast path -> exact zeros) ----
    {
        const float invS0 = Ss[r0l], invS1 = Ss[r1l];
        float* zr0 = zhat + (gr0 + r0l) * DD;
        float* zr1 = zhat + (gr0 + r1l) * DD;
        #pragma unroll
        for (int g = 0; g < 8; g++) {
            #pragma unroll
            for (int t = 0; t < 2; t++) {
                int d = wc * 128 + g * 16 + t * 8 + 2 * (lane & 3);
                int ii = (g * 2 + t) * 4;
                *(float2*)(zr0 + d) = make_float2(zac[ii + 0] * invS0, zac[ii + 1] * invS0);
                *(float2*)(zr1 + d) = make_float2(zac[ii + 2] * invS1, zac[ii + 3] * invS1);
            }
        }
    }
}

// ---------------- host ----------------
extern "C" void kernel_launch(void* const* d_in, const int* in_sizes, int n_in,
                              void* d_out, int out_size) {
    const float* z   = (const float*)d_in[0];
    const float* mem = (const float*)d_in[1];
    const int N = in_sizes[0] / DD;
    const int M = in_sizes[1] / DD;
    const int NCH = (M + CH - 1) / CH;

    float* zhat = (float*)d_out;                 // [N, 256]
    float* wout = zhat + (size_t)N * DD;         // [N, M]

    cudaFuncSetAttribute(mm_main, cudaFuncAttributeMaxDynamicSharedMemorySize, SM_TOT);

    mm_prep<<<NCH * CH, 256>>>(mem, M);
    mm_main<<<N / RB, TPB, SM_TOT>>>(z, wout, zhat, M, NCH);
}

// round 16
// speedup vs baseline: 1.1765x; 1.1196x over previous
#include <cuda_runtime.h>
#include <cuda_bf16.h>
#include <math.h>
#include <stdint.h>

#define DD    256
#define RB    64          // z rows per CTA
#define CH    64          // memory cols per chunk
#define TPB   256
#define LAMBF 0.002f
#define EPSN  1e-10f
#define EPSS  1e-12f
#define MAXM  2048
#define NCHMX 32

// pre-swizzled bf16 operand tiles (scratch via __device__ globals)
__device__ __align__(16) __nv_bfloat16 g_mn[MAXM * DD];   // m_norm rows, ldmatrix swizzle
__device__ __align__(16) __nv_bfloat16 g_mt[MAXM * DD];   // mem^T chunk-blocked, ldmatrix swizzle

// ---------------- helpers ----------------
__device__ __forceinline__ uint32_t smem_u32(const void* p) {
    uint32_t a;
    asm("{ .reg .u64 t; cvta.to.shared.u64 t, %1; cvt.u32.u64 %0, t; }" : "=r"(a) : "l"(p));
    return a;
}

#define LDSM4(r0, r1, r2, r3, a) \
    asm volatile("ldmatrix.sync.aligned.m8n8.x4.shared.b16 {%0,%1,%2,%3}, [%4];" \
                 : "=r"(r0), "=r"(r1), "=r"(r2), "=r"(r3) : "r"(a))

#define MMA16816(d, A, b0, b1) \
    asm volatile("mma.sync.aligned.m16n8k16.row.col.f32.bf16.bf16.f32 " \
                 "{%0,%1,%2,%3},{%4,%5,%6,%7},{%8,%9},{%0,%1,%2,%3};" \
                 : "+f"((d)[0]), "+f"((d)[1]), "+f"((d)[2]), "+f"((d)[3]) \
                 : "r"((A)[0]), "r"((A)[1]), "r"((A)[2]), "r"((A)[3]), "r"(b0), "r"(b1))

#define CPASYNC16(dst, src) \
    asm volatile("cp.async.cg.shared.global [%0], [%1], 16;" :: "r"(dst), "l"(src) : "memory")
#define CPCOMMIT() asm volatile("cp.async.commit_group;" ::: "memory")
#define CPWAIT(n)  asm volatile("cp.async.wait_group %0;" :: "n"(n) : "memory")

#define NBAR(id) asm volatile("bar.sync %0, 128;" :: "r"(id) : "memory")

__device__ __forceinline__ uint32_t bf2(float lo, float hi) {
    uint32_t r;
    asm("cvt.rn.bf16x2.f32 %0, %1, %2;" : "=r"(r) : "f"(hi), "f"(lo));
    return r;
}

// order-preserving float->uint encode (atomicMax on signed floats; fallback only)
__device__ __forceinline__ uint32_t encf(float x) {
    uint32_t u = __float_as_uint(x);
    return (u & 0x80000000u) ? ~u : (u | 0x80000000u);
}

// fast exp via MUFU (fallback path only): rel err ~1e-7; ex2(0)==1.0f exactly
__device__ __forceinline__ float fexp(float x) {
    float r;
    asm("ex2.approx.f32 %0, %1;" : "=f"(r) : "f"(x * 1.4426950408889634f));
    return r;
}

__device__ __forceinline__ float shrinkf(float w) {
    float d = w - LAMBF;
    return fmaxf(d, 0.f) * w / (fabsf(d) + EPSS);
}

// ---------------- prologue ----------------
__global__ void mm_prep(const float* __restrict__ mem, int M) {
    int m = blockIdx.x;
    int d = threadIdx.x;
    float v = (m < M) ? mem[(size_t)m * DD + d] : 0.f;
    float ss = v * v;
    #pragma unroll
    for (int o = 16; o; o >>= 1) ss += __shfl_xor_sync(0xffffffffu, ss, o);
    __shared__ float ws[8];
    __shared__ float sc;
    if ((d & 31) == 0) ws[d >> 5] = ss;
    __syncthreads();
    if (d == 0) {
        float t = 0.f;
        #pragma unroll
        for (int i = 0; i < 8; i++) t += ws[i];
        sc = sqrtf(t) + EPSN;
    }
    __syncthreads();
    g_mn[m * 256 + (((d >> 3) ^ (m & 7)) * 8) + (d & 7)] = __float2bfloat16(v / sc);
    int ch = m >> 6, c = m & 63;
    g_mt[ch * 16384 + d * 64 + (((c >> 3) ^ (d & 7)) * 8) + (c & 7)] = __float2bfloat16(v);
}

// ---------------- GEMM micro-kernels (R10 proven) ----------------
__device__ __forceinline__ void gemm1_reg(const uint32_t* Areg, uint32_t sB, int wc, int lane,
                                          float acc[16]) {
    const uint32_t h = lane >> 4;
    const uint32_t brow = wc * 32 + (lane & 15);
    const uint32_t bbase = sB + brow * 512;
    const uint32_t brx = brow & 7;
    uint32_t p[4], q[4];
    LDSM4(p[0], p[1], p[2], p[3], bbase + ((h ^ brx) << 4));
    #pragma unroll
    for (int kk = 0; kk < 16; kk++) {
        uint32_t cb = ((uint32_t)(kk * 2 + h) ^ brx) << 4;
        LDSM4(q[0], q[1], q[2], q[3], bbase + 16 * 512 + cb);
        MMA16816(acc + 0, (Areg + 4 * kk), p[0], p[2]);
        MMA16816(acc + 4, (Areg + 4 * kk), p[1], p[3]);
        if (kk < 15) {
            uint32_t cbn = ((uint32_t)((kk + 1) * 2 + h) ^ brx) << 4;
            LDSM4(p[0], p[1], p[2], p[3], bbase + cbn);
        }
        MMA16816(acc + 8,  (Areg + 4 * kk), q[0], q[2]);
        MMA16816(acc + 12, (Areg + 4 * kk), q[1], q[3]);
    }
}

__device__ __forceinline__ void gemm2(uint32_t sP, uint32_t sB2, int wr, int wc, int lane,
                                      float zac[64]) {
    const uint32_t h = lane >> 4;
    const uint32_t prow = wr * 16 + (lane & 15);
    const uint32_t pbase = sP + prow * 128;
    const uint32_t prx = prow & 7;
    const uint32_t drow = wc * 128 + (lane & 15);
    const uint32_t dbase = sB2 + drow * 128;
    const uint32_t drx = drow & 7;
    #pragma unroll
    for (int kk = 0; kk < 4; kk++) {
        uint32_t ca = ((uint32_t)(kk * 2 + h) ^ prx) << 4;
        uint32_t cb = ((uint32_t)(kk * 2 + h) ^ drx) << 4;
        uint32_t A[4];
        LDSM4(A[0], A[1], A[2], A[3], pbase + ca);
        #pragma unroll
        for (int g = 0; g < 8; g++) {
            uint32_t b0, b1, b2, b3;
            LDSM4(b0, b1, b2, b3, dbase + g * 2048 + cb);
            MMA16816(zac + (g * 2) * 4,     A, b0, b2);
            MMA16816(zac + (g * 2 + 1) * 4, A, b1, b3);
        }
    }
}

// full-tile copy (fallback path)
__device__ __forceinline__ void copyB(uint32_t sdst, const __nv_bfloat16* g) {
    const char* gp = (const char*)g;
    #pragma unroll
    for (int k = 0; k < 8; k++) {
        int idx = threadIdx.x + k * 256;
        CPASYNC16(sdst + idx * 16, gp + (size_t)idx * 16);
    }
}

// half-tile copy: group wc copies its own 16 KB half (rows wc*32..wc*32+31)
__device__ __forceinline__ void copyHalf(uint32_t sbuf, int ch, int wc, int gidx) {
    const char* gp = (const char*)g_mn + (size_t)ch * 32768 + wc * 16384;
    uint32_t d = sbuf + wc * 16384;
    #pragma unroll
    for (int k = 0; k < 8; k++)
        CPASYNC16(d + (gidx + k * 128) * 16, gp + (size_t)(gidx + k * 128) * 16);
}

// smem offsets (bytes) — R15 layout
#define A_OFF    0          // A tile (32K), intact for whole kernel
#define B1A_OFF  32768      // B dbl
#define B1B_OFF  65536
#define RMAX_OFF 98304      // fallback: 32 chunks x 32 pairs x 4B = 4K
#define P_OFF    98304      // phase A P tile (8K), aliases RMAX (after flags fixed)
#define TENC_OFF 106496     // 32 x 4B
#define FLG_OFF  106752     // 32 x 4B + anyflag slot
#define RED_OFF  106880     // 512 floats
#define ZS_OFF   108928
#define TS_OFF   109184
#define SS_OFF   109440
#define SM_TOT   109696

__global__ __launch_bounds__(TPB, 2) void mm_main(
    const float* __restrict__ z,
    float* __restrict__ wout,     // [N, M]
    float* __restrict__ zhat,     // [N, 256]
    int M, int NCH)
{
    extern __shared__ char smc[];
    const uint32_t sbase = smem_u32(smc);
    uint32_t* rmaxP = (uint32_t*)(smc + RMAX_OFF);
    uint32_t* tencP = (uint32_t*)(smc + TENC_OFF);
    int*      flg  = (int*)(smc + FLG_OFF);
    float*    red  = (float*)(smc + RED_OFF);
    float*    Zs   = (float*)(smc + ZS_OFF);
    float*    Ts   = (float*)(smc + TS_OFF);
    float*    Ss   = (float*)(smc + SS_OFF);

    const int tid = threadIdx.x, wid = tid >> 5, lane = tid & 31;
    const int wr = wid >> 1, wc = wid & 1;
    const long long gr0 = (long long)blockIdx.x * RB;
    const int r0l = wr * 16 + (lane >> 2), r1l = r0l + 8;
    const int pr  = wr * 8 + (lane >> 2);   // row-pair index (fallback)
    const int gidx = (wid >> 1) * 32 + lane; // 0..127 within wc-group

    const uint32_t sA = sbase + A_OFF;

    // ---- build A tile ----
    #pragma unroll 1
    for (int i = 0; i < 8; i++) {
        int r = wid * 8 + i;
        const float4* zr = (const float4*)(z + (gr0 + r) * DD);
        float4 a = zr[lane * 2], b = zr[lane * 2 + 1];
        float ss = a.x*a.x + a.y*a.y + a.z*a.z + a.w*a.w
                 + b.x*b.x + b.y*b.y + b.z*b.z + b.w*b.w;
        #pragma unroll
        for (int o = 16; o; o >>= 1) ss += __shfl_xor_sync(0xffffffffu, ss, o);
        float inv = 1.f / (sqrtf(ss) + EPSN);
        uint4 u;
        u.x = bf2(a.x * inv, a.y * inv); u.y = bf2(a.z * inv, a.w * inv);
        u.z = bf2(b.x * inv, b.y * inv); u.w = bf2(b.z * inv, b.w * inv);
        *(uint4*)(smc + A_OFF + r * 512 + ((lane ^ (r & 7)) * 16)) = u;
    }
    __syncthreads();

    // ---- hoist A fragments to registers (A tile stays intact in SMEM) ----
    uint32_t Areg[64];
    {
        const uint32_t h = lane >> 4;
        const uint32_t arow = wr * 16 + (lane & 15);
        const uint32_t abase = sA + arow * 512;
        const uint32_t arx = arow & 7;
        #pragma unroll
        for (int kk = 0; kk < 16; kk++) {
            uint32_t ca = ((uint32_t)(kk * 2 + h) ^ arx) << 4;
            LDSM4(Areg[4*kk], Areg[4*kk+1], Areg[4*kk+2], Areg[4*kk+3], abase + ca);
        }
    }

    // ---- hoisted zero-fill row pointers (advanced by CH per chunk) ----
    float4* fp[4];
    {
        int cb = (tid & 15) * 4;
        #pragma unroll
        for (int k = 0; k < 4; k++)
            fp[k] = (float4*)(wout + (gr0 + (tid >> 4) + k * 16) * (long long)M + cb);
    }
    const int cbase = (tid & 15) * 4;

    // ========== PASS 1: group-local pipeline; gmax/gmin only (no flags, no Z) ==========
    // Sound CTA-wide test: Z_r >= M*exp(gmin) and s <= gmax, so every w <= lambda if
    // gmax - gmin <= ln(lambda*M) - margin. Pads (sim==0) only widen the range: safe.
    float gmx = -3.f, gmn = 3.f;
    copyHalf(sbase + B1A_OFF, 0, wc, gidx); CPCOMMIT();
    for (int ch = 0; ch < NCH; ch++) {
        CPWAIT(0);
        NBAR(1 + wc);   // group-local: copies of half(ch) visible; gemm(ch-1) drained
        if (ch + 1 < NCH) {
            copyHalf(sbase + (((ch + 1) & 1) ? B1B_OFF : B1A_OFF), ch + 1, wc, gidx);
            CPCOMMIT();
        }
        // zero-fill this chunk's w_hat region (overlaps gemm LDSM warm-up)
        if (ch * CH + cbase < M) {   // M % 4 == 0
            const float4 zero4 = make_float4(0.f, 0.f, 0.f, 0.f);
            #pragma unroll
            for (int k = 0; k < 4; k++) *fp[k] = zero4;
        }
        #pragma unroll
        for (int k = 0; k < 4; k++) fp[k] += CH / 4;
        float acc[16] = {};
        gemm1_reg(Areg, sbase + ((ch & 1) ? B1B_OFF : B1A_OFF), wc, lane, acc);
        #pragma unroll
        for (int nt = 0; nt < 4; nt++) {
            float u0 = fmaxf(acc[nt * 4 + 0], acc[nt * 4 + 1]);
            float u1 = fmaxf(acc[nt * 4 + 2], acc[nt * 4 + 3]);
            float v0 = fminf(acc[nt * 4 + 0], acc[nt * 4 + 1]);
            float v1 = fminf(acc[nt * 4 + 2], acc[nt * 4 + 3]);
            gmx = fmaxf(gmx, fmaxf(u0, u1));
            gmn = fminf(gmn, fminf(v0, v1));
        }
    }
    // warp reduce, then CTA reduce
    #pragma unroll
    for (int o = 16; o; o >>= 1) {
        gmx = fmaxf(gmx, __shfl_xor_sync(0xffffffffu, gmx, o));
        gmn = fminf(gmn, __shfl_xor_sync(0xffffffffu, gmn, o));
    }
    __syncthreads();
    if (lane == 0) { red[wid] = gmx; red[8 + wid] = gmn; }
    __syncthreads();
    if (tid == 0) {
        float mx = red[0], mn2 = red[8];
        #pragma unroll
        for (int j = 1; j < 8; j++) { mx = fmaxf(mx, red[j]); mn2 = fminf(mn2, red[8 + j]); }
        flg[32] = (mx - mn2 > logf(LAMBF * (float)M) - 1e-3f) ? 1 : 0;
    }
    __syncthreads();
    const int anyflag = flg[32];

    // ========== FALLBACK (rare): exact Z + per-chunk flags + phase A ==========
    float s0 = 0.f, s1 = 0.f;
    float zac[64] = {};
    if (anyflag) {
        for (int i = tid; i < NCH * 32; i += TPB) rmaxP[i] = 0u;
        __syncthreads();
        // exact Z pass (fexp) + per-(pair,chunk) max; sims bit-identical to pass 1
        float z0 = 0.f, z1 = 0.f;
        copyB(sbase + B1A_OFF, g_mn); CPCOMMIT();
        for (int ch = 0; ch < NCH; ch++) {
            CPWAIT(0);
            __syncthreads();
            if (ch + 1 < NCH) {
                copyB(sbase + (((ch + 1) & 1) ? B1B_OFF : B1A_OFF),
                      g_mn + (size_t)(ch + 1) * CH * DD);
                CPCOMMIT();
            }
            float acc[16] = {};
            gemm1_reg(Areg, sbase + ((ch & 1) ? B1B_OFF : B1A_OFF), wc, lane, acc);
            float m = acc[0];
            #pragma unroll
            for (int nt = 0; nt < 4; nt++) {
                z0 += fexp(acc[nt * 4 + 0]) + fexp(acc[nt * 4 + 1]);
                z1 += fexp(acc[nt * 4 + 2]) + fexp(acc[nt * 4 + 3]);
                m = fmaxf(m, fmaxf(fmaxf(acc[nt * 4 + 0], acc[nt * 4 + 1]),
                                   fmaxf(acc[nt * 4 + 2], acc[nt * 4 + 3])));
            }
            m = fmaxf(m, __shfl_xor_sync(0xffffffffu, m, 1));
            m = fmaxf(m, __shfl_xor_sync(0xffffffffu, m, 2));
            if ((lane & 3) == 0)
                atomicMax(&rmaxP[ch * 32 + pr], encf(m));
        }
        __syncthreads();
        red[r0l * 8 + wc * 4 + (lane & 3)] = z0;
        red[r1l * 8 + wc * 4 + (lane & 3)] = z1;
        __syncthreads();
        const float padc = (float)(NCH * CH - M);
        if (tid < 64) {
            float s = 0.f;
            #pragma unroll
            for (int j = 0; j < 8; j++) s += red[tid * 8 + j];
            s -= padc;                           // pads exact: sim 0 -> fexp 1
            Zs[tid] = 1.0f / s;
            Ts[tid] = logf(LAMBF * s) - 1e-3f;   // exact conservative threshold
        }
        __syncthreads();
        if (tid < 32) {
            int row0 = (tid >> 3) * 16 + (tid & 7);
            tencP[tid] = encf(fminf(Ts[row0], Ts[row0 + 8]));
        }
        __syncthreads();
        if (tid < NCH) {
            int f = 0;
            #pragma unroll 4
            for (int p = 0; p < 32; p++) f |= (rmaxP[tid * 32 + p] > tencP[p]);
            flg[tid] = f;
        }
        __syncthreads();

        const float invZ0 = Zs[r0l], invZ1 = Zs[r1l];
        const float T0 = Ts[r0l],    T1 = Ts[r1l];
        for (int ch = 0; ch < NCH; ch++) {
            if (!flg[ch]) continue;
            copyB(sbase + B1A_OFF, g_mn + (size_t)ch * CH * DD);
            CPCOMMIT(); CPWAIT(0);
            __syncthreads();
            float acc[16] = {};
            gemm1_reg(Areg, sbase + B1A_OFF, wc, lane, acc);   // bit-identical sims
            float* w0 = wout + (gr0 + r0l) * (long long)M;
            float* w1 = wout + (gr0 + r1l) * (long long)M;
            #pragma unroll
            for (int nt = 0; nt < 4; nt++) {
                int cl  = wc * 32 + nt * 8 + 2 * (lane & 3);
                int col = ch * CH + cl;
                float h00 = 0.f, h01 = 0.f, h10 = 0.f, h11 = 0.f;
                if (col < M) {
                    float a0 = acc[nt*4+0], a1 = acc[nt*4+1], a2 = acc[nt*4+2], a3 = acc[nt*4+3];
                    if (a0 > T0) h00 = shrinkf(fexp(a0) * invZ0);
                    if (a1 > T0) h01 = shrinkf(fexp(a1) * invZ0);
                    if (a2 > T1) h10 = shrinkf(fexp(a2) * invZ1);
                    if (a3 > T1) h11 = shrinkf(fexp(a3) * invZ1);
                    s0 += h00 + h01; s1 += h10 + h11;
                    *(float2*)(w0 + col) = make_float2(h00, h01);   // unnormalized
                    *(float2*)(w1 + col) = make_float2(h10, h11);
                }
                *(uint32_t*)(smc + P_OFF + r0l * 128 + (((cl >> 3) ^ (r0l & 7)) << 4) + (cl & 7) * 2)
                    = bf2(h00, h01);
                *(uint32_t*)(smc + P_OFF + r1l * 128 + (((cl >> 3) ^ (r1l & 7)) << 4) + (cl & 7) * 2)
                    = bf2(h10, h11);
            }
            __syncthreads();
            copyB(sbase + B1B_OFF, g_mt + (size_t)ch * CH * DD);
            CPCOMMIT(); CPWAIT(0);
            __syncthreads();
            gemm2(sbase + P_OFF, sbase + B1B_OFF, wr, wc, lane, zac);
            __syncthreads();
        }
    }

    // ---- S reduction ----
    __syncthreads();
    red[r0l * 8 + wc * 4 + (lane & 3)] = s0;
    red[r1l * 8 + wc * 4 + (lane & 3)] = s1;
    __syncthreads();
    if (tid < 64) {
        float s = 0.f;
        #pragma unroll
        for (int j = 0; j < 8; j++) s += red[tid * 8 + j];
        Ss[tid] = 1.0f / (s + EPSS);
    }
    __syncthreads();

    // ---- fixup flagged chunks: w_hat *= invS ----
    if (anyflag) {
        for (int ch = 0; ch < NCH; ch++) {
            if (!flg[ch]) continue;
            for (int idx = tid; idx < 64 * 16; idx += TPB) {
                int r = idx >> 4;
                int c4 = ch * CH + (idx & 15) * 4;
                if (c4 < M) {
                    float4* p = (float4*)(wout + (gr0 + r) * (long long)M + c4);
                    float4 v = *p; float s = Ss[r];
                    v.x *= s; v.y *= s; v.z *= s; v.w *= s;
                    *p = v;
                }
            }
        }
        __syncthreads();
    }

    // ---- z_hat epilogue (zac==0 on fast path -> exact zeros) ----
    {
        const float invS0 = Ss[r0l], invS1 = Ss[r1l];
        float* zr0 = zhat + (gr0 + r0l) * DD;
        float* zr1 = zhat + (gr0 + r1l) * DD;
        #pragma unroll
        for (int g = 0; g < 8; g++) {
            #pragma unroll
            for (int t = 0; t < 2; t++) {
                int d = wc * 128 + g * 16 + t * 8 + 2 * (lane & 3);
                int ii = (g * 2 + t) * 4;
                *(float2*)(zr0 + d) = make_float2(zac[ii + 0] * invS0, zac[ii + 1] * invS0);
                *(float2*)(zr1 + d) = make_float2(zac[ii + 2] * invS1, zac[ii + 3] * invS1);
            }
        }
    }
}

// ---------------- host ----------------
extern "C" void kernel_launch(void* const* d_in, const int* in_sizes, int n_in,
                              void* d_out, int out_size) {
    const float* z   = (const float*)d_in[0];
    const float* mem = (const float*)d_in[1];
    const int N = in_sizes[0] / DD;
    const int M = in_sizes[1] / DD;
    const int NCH = (M + CH - 1) / CH;

    float* zhat = (float*)d_out;                 // [N, 256]
    float* wout = zhat + (size_t)N * DD;         // [N, M]

    cudaFuncSetAttribute(mm_main, cudaFuncAttributeMaxDynamicSharedMemorySize, SM_TOT);

    mm_prep<<<NCH * CH, 256>>>(mem, M);
    mm_main<<<N / RB, TPB, SM_TOT>>>(z, wout, zhat, M, NCH);
}